// round 14
// baseline (speedup 1.0000x reference)
#include <cuda_runtime.h>
#include <cstdint>

// CompressK: mean-pool over sliding windows of 32 rows, stride 16.
// k: (BATCH*SEQ_LEN, 4, 128) fp32 -> row = 512 floats = 128 float4
// out: (4092, 4, 128) fp32 followed by cu_comp (BATCH+1) as fp32 values.
//
// R13 (26.6us) lineage: CH=8, full-row blocks, 512 threads, grid 512,
// double-buffered smem combine. NEW: FOUR block-sums per barrier
// interval -> 3 barriers/block (was 5). 512 threads = 4 groups x 128 f4
// cols; group g computes the full 16-row sum of S_{t+g} as two
// sequential MLP-8 load batches (register footprint unchanged).

#define BATCH 4
#define SEQ_LEN 16384
#define ROW_FLOATS 512
#define ROW_F4 128
#define CHUNKS_PER_BATCH 1023     // (16384-32)/16 + 1
#define TOTAL_CHUNKS (BATCH * CHUNKS_PER_BATCH)   // 4092
#define CH 8
#define SEGS_PER_BATCH ((CHUNKS_PER_BATCH + CH - 1) / CH)    // 128
#define OUT_FLOATS ((size_t)TOTAL_CHUNKS * ROW_FLOATS)       // 2,095,104
#define NTHREADS 512

__global__ __launch_bounds__(NTHREADS, 3) void compress_k_kernel(
    const float4* __restrict__ k4, float* __restrict__ out)
{
    __shared__ float4 part[2][4][ROW_F4];   // [buf][group][f4 col] = 16 KB

    const int tid  = threadIdx.x;           // 0..511
    const int col4 = tid & 127;             // float4 column
    const int g    = tid >> 7;              // group 0..3

    const int batch = blockIdx.x / SEGS_PER_BATCH;
    const int seg   = blockIdx.x % SEGS_PER_BATCH;

    // Fused cu_comp tail (fp32 values; exact for these magnitudes)
    if (blockIdx.x == 0 && tid <= BATCH) {
        out[OUT_FLOATS + tid] = (float)(tid * CHUNKS_PER_BATCH);
    }

    const int c_begin = seg * CH;
    int nch = CHUNKS_PER_BATCH - c_begin;
    if (nch > CH) nch = CH;                  // 8, or 7 on the last segment

    const size_t base_row = (size_t)batch * SEQ_LEN + (size_t)c_begin * 16;
    const float4* base = k4 + base_row * ROW_F4 + col4;

    const float* partf = (const float*)part;   // scalar view
    const float inv32 = 1.0f / 32.0f;

    const size_t out_base = ((size_t)batch * CHUNKS_PER_BATCH + c_begin) * ROW_FLOATS + tid;

    // ---- prologue: block-sum S_0 (quarter-split, MLP-4) ----
    float sPrev;
    {
        const float4* p = base + (size_t)g * 4 * ROW_F4;  // rows g*4..g*4+3
        float4 v0 = p[0 * ROW_F4];
        float4 v1 = p[1 * ROW_F4];
        float4 v2 = p[2 * ROW_F4];
        float4 v3 = p[3 * ROW_F4];
        float4 ps;
        ps.x = (v0.x + v1.x) + (v2.x + v3.x);
        ps.y = (v0.y + v1.y) + (v2.y + v3.y);
        ps.z = (v0.z + v1.z) + (v2.z + v3.z);
        ps.w = (v0.w + v1.w) + (v2.w + v3.w);
        part[0][g][col4] = ps;
        __syncthreads();
        sPrev = (partf[0 * ROW_FLOATS + tid] + partf[1 * ROW_FLOATS + tid])
              + (partf[2 * ROW_FLOATS + tid] + partf[3 * ROW_FLOATS + tid]);
    }

    // ---- main loop: block-sums S_t..S_{t+3} per barrier interval ----
    int buf = 1;
    for (int t = 1; t <= nch; t += 4) {
        const int idx = t + g;               // this group's block-sum
        if (idx <= nch) {
            const float4* p = base + (size_t)idx * 16 * ROW_F4;
            // batch 1: rows 0..7 (8 independent LDG.128)
            float4 v0 = p[0 * ROW_F4];
            float4 v1 = p[1 * ROW_F4];
            float4 v2 = p[2 * ROW_F4];
            float4 v3 = p[3 * ROW_F4];
            float4 v4 = p[4 * ROW_F4];
            float4 v5 = p[5 * ROW_F4];
            float4 v6 = p[6 * ROW_F4];
            float4 v7 = p[7 * ROW_F4];
            float4 a;
            a.x = ((v0.x + v1.x) + (v2.x + v3.x)) + ((v4.x + v5.x) + (v6.x + v7.x));
            a.y = ((v0.y + v1.y) + (v2.y + v3.y)) + ((v4.y + v5.y) + (v6.y + v7.y));
            a.z = ((v0.z + v1.z) + (v2.z + v3.z)) + ((v4.z + v5.z) + (v6.z + v7.z));
            a.w = ((v0.w + v1.w) + (v2.w + v3.w)) + ((v4.w + v5.w) + (v6.w + v7.w));
            // batch 2: rows 8..15 (same 8 registers reused)
            v0 = p[8  * ROW_F4];
            v1 = p[9  * ROW_F4];
            v2 = p[10 * ROW_F4];
            v3 = p[11 * ROW_F4];
            v4 = p[12 * ROW_F4];
            v5 = p[13 * ROW_F4];
            v6 = p[14 * ROW_F4];
            v7 = p[15 * ROW_F4];
            a.x += ((v0.x + v1.x) + (v2.x + v3.x)) + ((v4.x + v5.x) + (v6.x + v7.x));
            a.y += ((v0.y + v1.y) + (v2.y + v3.y)) + ((v4.y + v5.y) + (v6.y + v7.y));
            a.z += ((v0.z + v1.z) + (v2.z + v3.z)) + ((v4.z + v5.z) + (v6.z + v7.z));
            a.w += ((v0.w + v1.w) + (v2.w + v3.w)) + ((v4.w + v5.w) + (v6.w + v7.w));
            part[buf][g][col4] = a;
        }

        __syncthreads();

        const float* pb = partf + (size_t)buf * 4 * ROW_FLOATS;
        float s0 = pb[0 * ROW_FLOATS + tid];
        float s1 = pb[1 * ROW_FLOATS + tid];
        float s2 = pb[2 * ROW_FLOATS + tid];
        float s3 = pb[3 * ROW_FLOATS + tid];

        // chunk c = (S_c + S_{c+1}) / 32
        out[out_base + (size_t)(t - 1) * ROW_FLOATS] = (sPrev + s0) * inv32;
        if (t + 1 <= nch)
            out[out_base + (size_t)t * ROW_FLOATS] = (s0 + s1) * inv32;
        if (t + 2 <= nch)
            out[out_base + (size_t)(t + 1) * ROW_FLOATS] = (s1 + s2) * inv32;
        if (t + 3 <= nch)
            out[out_base + (size_t)(t + 2) * ROW_FLOATS] = (s2 + s3) * inv32;

        sPrev = s3;   // valid whenever another iteration follows
        buf ^= 1;
    }
}

extern "C" void kernel_launch(void* const* d_in, const int* in_sizes, int n_in,
                              void* d_out, int out_size)
{
    const float4* k4 = (const float4*)d_in[0];

    dim3 grid(BATCH * SEGS_PER_BATCH);   // 512
    compress_k_kernel<<<grid, NTHREADS>>>(k4, (float*)d_out);
}